// round 14
// baseline (speedup 1.0000x reference)
#include <cuda_runtime.h>
#include <math.h>
#include <stdint.h>

// Problem constants
#define N_W   80000
#define N_D   16000
#define E_WW  200000
#define E_WD  200000
#define HF    512      // H*F = 4*128
#define F_OUT 128
#define H_N   4

// GEMM tiling
#define BM 128
#define BN 128
#define BK 16
#define NSTAGE 4
#define AS_STRIDE 28
#define BS_STRIDE 136
#define AS_TILE (BM * AS_STRIDE)
#define BS_TILE (BK * BS_STRIDE)
#define DYN_SMEM ((NSTAGE * (AS_TILE + BS_TILE)) * 4)   // 92160 bytes

// ---------------------------------------------------------------------------
// Static device scratch (allocation-free rule)
// ---------------------------------------------------------------------------
__device__ float g_z_ww[(size_t)N_W * HF];
__device__ float g_z_wd[(size_t)N_W * HF];
__device__ float g_zd_wd[(size_t)N_D * HF];
__device__ float g_el_ww[N_W * H_N];
__device__ float g_er_ww[N_W * H_N];
__device__ float g_el_wd[N_W * H_N];
__device__ float g_er_wd[N_D * H_N];
__device__ float g_xw1[(size_t)N_W * F_OUT];
__device__ float g_xd1[(size_t)N_D * F_OUT];
__device__ float g_xw_r[(size_t)N_W * 256];
__device__ float g_xd_r[(size_t)N_D * 256];
__device__ float g_w0a[256 * 512];
__device__ float g_w0b[256 * 512];
__device__ float g_w1a[128 * 512];
__device__ float g_w1b[128 * 512];
__device__ int   g_deg_ww[N_W];
__device__ int   g_deg_wd[N_D];
__device__ int   g_beg_ww[N_W];
__device__ int   g_beg_wd[N_D];
__device__ int   g_cur_ww[N_W];
__device__ int   g_cur_wd[N_D];
__device__ int   g_ci_ww[E_WW];
__device__ int   g_ci_wd[E_WD];
__device__ int   g_total[2];

// ---------------------------------------------------------------------------
// helpers
// ---------------------------------------------------------------------------
__device__ __forceinline__ uint32_t f2tf(float x) {
    uint32_t r;
    asm("cvt.rna.tf32.f32 %0, %1;" : "=r"(r) : "f"(x));
    return r;
}
__device__ __forceinline__ float roundtf(float x) {
    return __uint_as_float(f2tf(x));
}
__device__ __forceinline__ void cpa16(uint32_t dst, const float* src) {
    asm volatile("cp.async.cg.shared.global [%0], [%1], 16;" :: "r"(dst), "l"(src));
}
__device__ __forceinline__ void cp_commit() {
    asm volatile("cp.async.commit_group;");
}
__device__ __forceinline__ void mma_tf32(float* d, const uint32_t* a, const uint32_t* b) {
    asm volatile(
        "mma.sync.aligned.m16n8k8.row.col.f32.tf32.tf32.f32 "
        "{%0,%1,%2,%3}, {%4,%5,%6,%7}, {%8,%9}, {%0,%1,%2,%3};\n"
        : "+f"(d[0]), "+f"(d[1]), "+f"(d[2]), "+f"(d[3])
        : "r"(a[0]), "r"(a[1]), "r"(a[2]), "r"(a[3]), "r"(b[0]), "r"(b[1]));
}

// ---------------------------------------------------------------------------
// tf32 pre-rounding kernels
// ---------------------------------------------------------------------------
__global__ void k_round(const float4* __restrict__ src, float4* __restrict__ dst, int n4) {
    int i = blockIdx.x * blockDim.x + threadIdx.x;
    if (i < n4) {
        float4 v = src[i];
        v.x = roundtf(v.x); v.y = roundtf(v.y);
        v.z = roundtf(v.z); v.w = roundtf(v.w);
        dst[i] = v;
    }
}

__global__ void k_round4(const float4* s0, float4* d0, int n0,
                         const float4* s1, float4* d1, int n1,
                         const float4* s2, float4* d2, int n2,
                         const float4* s3, float4* d3, int n3) {
    int i = blockIdx.x * blockDim.x + threadIdx.x;
    const float4* s; float4* d; int j = i;
    if (j < n0) { s = s0; d = d0; }
    else { j -= n0;
        if (j < n1) { s = s1; d = d1; }
        else { j -= n1;
            if (j < n2) { s = s2; d = d2; }
            else { j -= n2;
                if (j < n3) { s = s3; d = d3; }
                else return;
            }
        }
    }
    float4 v = s[j];
    v.x = roundtf(v.x); v.y = roundtf(v.y);
    v.z = roundtf(v.z); v.w = roundtf(v.w);
    d[j] = v;
}

// ---------------------------------------------------------------------------
// Merged CSR build
// ---------------------------------------------------------------------------
__global__ void k_zero_multi(int* p0, int n0, int* p1, int n1,
                             int* p2, int n2, int* p3, int n3,
                             int* p4, int n4) {
    int i = blockIdx.x * blockDim.x + threadIdx.x;
    int* p; int j = i;
    if (j < n0) p = p0;
    else { j -= n0;
        if (j < n1) p = p1;
        else { j -= n1;
            if (j < n2) p = p2;
            else { j -= n2;
                if (j < n3) p = p3;
                else { j -= n3;
                    if (j < n4) p = p4;
                    else return;
                }
            }
        }
    }
    p[j] = 0;
}

__global__ void k_hist2(const int* __restrict__ dst_ww, const int* __restrict__ dst_wd,
                        int* __restrict__ deg_ww, int* __restrict__ deg_wd) {
    int i = blockIdx.x * blockDim.x + threadIdx.x;
    if (i < E_WW) atomicAdd(&deg_ww[dst_ww[i]], 1);
    else if (i < E_WW + E_WD) atomicAdd(&deg_wd[dst_wd[i - E_WW]], 1);
}

__global__ void k_offsets2(const int* __restrict__ deg_ww, int* __restrict__ beg_ww,
                           const int* __restrict__ deg_wd, int* __restrict__ beg_wd,
                           int* __restrict__ total) {
    int i = blockIdx.x * blockDim.x + threadIdx.x;
    int lane = threadIdx.x & 31;
    const int* deg; int* beg; int* tot; int j; bool ok = true;
    if (i < N_W) { deg = deg_ww; beg = beg_ww; tot = total; j = i; }
    else if (i < N_W + N_D) { deg = deg_wd; beg = beg_wd; tot = total + 1; j = i - N_W; }
    else ok = false;
    int v = ok ? deg[j] : 0;
    int s = v;
    #pragma unroll
    for (int off = 1; off < 32; off <<= 1) {
        int t = __shfl_up_sync(0xffffffffu, s, off);
        if (lane >= off) s += t;
    }
    int wtot = __shfl_sync(0xffffffffu, s, 31);
    int base = 0;
    if (lane == 31 && ok) base = atomicAdd(tot, wtot);
    base = __shfl_sync(0xffffffffu, base, 31);
    if (ok) beg[j] = base + s - v;
}

__global__ void k_scatter2(const int* __restrict__ ww_src, const int* __restrict__ ww_dst,
                           const int* __restrict__ wd_src, const int* __restrict__ wd_dst,
                           const int* __restrict__ beg_ww, int* __restrict__ cur_ww,
                           int* __restrict__ ci_ww,
                           const int* __restrict__ beg_wd, int* __restrict__ cur_wd,
                           int* __restrict__ ci_wd) {
    int i = blockIdx.x * blockDim.x + threadIdx.x;
    if (i < E_WW) {
        int d = ww_dst[i];
        int p = atomicAdd(&cur_ww[d], 1);
        ci_ww[beg_ww[d] + p] = ww_src[i];
    } else if (i < E_WW + E_WD) {
        int j = i - E_WW;
        int d = wd_dst[j];
        int p = atomicAdd(&cur_wd[d], 1);
        ci_wd[beg_wd[d] + p] = wd_src[j];
    }
}

// ---------------------------------------------------------------------------
// TF32 tensor-core GEMM (3 segments in one launch)
// ---------------------------------------------------------------------------
__global__ __launch_bounds__(512, 2) void k_gemm3(
    const float* __restrict__ A0, const float* __restrict__ B0, float* __restrict__ C0,
    const float* __restrict__ v10, const float* __restrict__ v20,
    float* __restrict__ o10, float* __restrict__ o20, int t0,
    const float* __restrict__ A1, const float* __restrict__ B1, float* __restrict__ C1,
    const float* __restrict__ v11, const float* __restrict__ v21,
    float* __restrict__ o11, float* __restrict__ o21, int t1,
    const float* __restrict__ A2, const float* __restrict__ B2, float* __restrict__ C2,
    const float* __restrict__ v12, const float* __restrict__ v22,
    float* __restrict__ o12, float* __restrict__ o22,
    int K) {
    extern __shared__ __align__(16) float dsm[];
    __shared__ float sdot1[BM];
    __shared__ float sdot2[BM];

    float* AsBase = dsm;
    float* BsBase = dsm + NSTAGE * AS_TILE;

    int by = blockIdx.y;
    const float *A, *Bm, *v1, *v2;
    float *C, *o1, *o2;
    if (by < t0) { A = A0; Bm = B0; C = C0; v1 = v10; v2 = v20; o1 = o10; o2 = o20; }
    else if (by < t0 + t1) { by -= t0; A = A1; Bm = B1; C = C1; v1 = v11; v2 = v21; o1 = o11; o2 = o21; }
    else { by -= t0 + t1; A = A2; Bm = B2; C = C2; v1 = v12; v2 = v22; o1 = o12; o2 = o22; }

    int tid = threadIdx.x;
    int lane = tid & 31, wid = tid >> 5;
    int g = lane >> 2, t4 = lane & 3;
    int wm = wid & 3, wn = wid >> 2;
    int bm = by * BM;
    int h  = blockIdx.x;
    int bn = h * BN;

    if (tid < BM) { sdot1[tid] = 0.f; sdot2[tid] = 0.f; }

    int a_row = tid >> 2;
    int a_kq  = (tid & 3) * 4;
    int b_row = tid >> 5;
    int b_nc  = (tid & 31) * 4;

    const float* Ap = A + (size_t)bm * K;

    uint32_t as_base = (uint32_t)__cvta_generic_to_shared(AsBase);
    uint32_t bs_base = (uint32_t)__cvta_generic_to_shared(BsBase);
    const uint32_t AS_BUF = AS_TILE * 4;
    const uint32_t BS_BUF = BS_TILE * 4;

    float acc[2][4][4] = {};

    int nk = K / BK;

    #pragma unroll
    for (int st = 0; st < NSTAGE - 1; st++) {
        int k0 = st * BK;
        cpa16(as_base + st * AS_BUF + (a_row * AS_STRIDE + a_kq) * 4,
              Ap + (size_t)a_row * K + k0 + a_kq);
        cpa16(bs_base + st * BS_BUF + (b_row * BS_STRIDE + b_nc) * 4,
              Bm + (size_t)(k0 + b_row) * 512 + bn + b_nc);
        cp_commit();
    }

    for (int kt = 0; kt < nk; kt++) {
        int st = kt & (NSTAGE - 1);
        asm volatile("cp.async.wait_group %0;" :: "n"(NSTAGE - 2));
        __syncthreads();

        if (kt + NSTAGE - 1 < nk) {
            int kf = kt + NSTAGE - 1;
            int stn = kf & (NSTAGE - 1);
            int k0 = kf * BK;
            cpa16(as_base + stn * AS_BUF + (a_row * AS_STRIDE + a_kq) * 4,
                  Ap + (size_t)a_row * K + k0 + a_kq);
            cpa16(bs_base + stn * BS_BUF + (b_row * BS_STRIDE + b_nc) * 4,
                  Bm + (size_t)(k0 + b_row) * 512 + bn + b_nc);
        }
        cp_commit();

        const float* As_st = AsBase + st * AS_TILE;
        const float* Bs_st = BsBase + st * BS_TILE;

        #pragma unroll
        for (int s = 0; s < 2; s++) {
            uint32_t a[2][4], b[4][2];
            #pragma unroll
            for (int mi = 0; mi < 2; mi++) {
                int r = wm * 32 + mi * 16;
                a[mi][0] = __float_as_uint(As_st[(r + g) * AS_STRIDE + s * 8 + t4]);
                a[mi][1] = __float_as_uint(As_st[(r + 8 + g) * AS_STRIDE + s * 8 + t4]);
                a[mi][2] = __float_as_uint(As_st[(r + g) * AS_STRIDE + s * 8 + t4 + 4]);
                a[mi][3] = __float_as_uint(As_st[(r + 8 + g) * AS_STRIDE + s * 8 + t4 + 4]);
            }
            #pragma unroll
            for (int nj = 0; nj < 4; nj++) {
                int c = wn * 32 + nj * 8 + g;
                b[nj][0] = __float_as_uint(Bs_st[(s * 8 + t4) * BS_STRIDE + c]);
                b[nj][1] = __float_as_uint(Bs_st[(s * 8 + t4 + 4) * BS_STRIDE + c]);
            }
            #pragma unroll
            for (int mi = 0; mi < 2; mi++)
                #pragma unroll
                for (int nj = 0; nj < 4; nj++)
                    mma_tf32(acc[mi][nj], a[mi], b[nj]);
        }
    }

    #pragma unroll
    for (int mi = 0; mi < 2; mi++) {
        int r0 = bm + wm * 32 + mi * 16 + g;
        int r1 = r0 + 8;
        #pragma unroll
        for (int nj = 0; nj < 4; nj++) {
            int c = bn + wn * 32 + nj * 8 + 2 * t4;
            *(float2*)(C + (size_t)r0 * 512 + c) = make_float2(acc[mi][nj][0], acc[mi][nj][1]);
            *(float2*)(C + (size_t)r1 * 512 + c) = make_float2(acc[mi][nj][2], acc[mi][nj][3]);
        }
    }

    if (o1 || o2) {
        float w1v[4][2], w2v[4][2];
        #pragma unroll
        for (int nj = 0; nj < 4; nj++) {
            int c = wn * 32 + nj * 8 + 2 * t4;
            if (o1) { w1v[nj][0] = v1[h * 128 + c]; w1v[nj][1] = v1[h * 128 + c + 1]; }
            if (o2) { w2v[nj][0] = v2[h * 128 + c]; w2v[nj][1] = v2[h * 128 + c + 1]; }
        }
        #pragma unroll
        for (int mi = 0; mi < 2; mi++) {
            float p0 = 0.f, p1 = 0.f, q0 = 0.f, q1 = 0.f;
            #pragma unroll
            for (int nj = 0; nj < 4; nj++) {
                if (o1) {
                    p0 += acc[mi][nj][0] * w1v[nj][0] + acc[mi][nj][1] * w1v[nj][1];
                    p1 += acc[mi][nj][2] * w1v[nj][0] + acc[mi][nj][3] * w1v[nj][1];
                }
                if (o2) {
                    q0 += acc[mi][nj][0] * w2v[nj][0] + acc[mi][nj][1] * w2v[nj][1];
                    q1 += acc[mi][nj][2] * w2v[nj][0] + acc[mi][nj][3] * w2v[nj][1];
                }
            }
            p0 += __shfl_down_sync(0xffffffffu, p0, 2, 4);
            p0 += __shfl_down_sync(0xffffffffu, p0, 1, 4);
            p1 += __shfl_down_sync(0xffffffffu, p1, 2, 4);
            p1 += __shfl_down_sync(0xffffffffu, p1, 1, 4);
            q0 += __shfl_down_sync(0xffffffffu, q0, 2, 4);
            q0 += __shfl_down_sync(0xffffffffu, q0, 1, 4);
            q1 += __shfl_down_sync(0xffffffffu, q1, 2, 4);
            q1 += __shfl_down_sync(0xffffffffu, q1, 1, 4);
            if (t4 == 0) {
                int lr = wm * 32 + mi * 16 + g;
                if (o1) { atomicAdd(&sdot1[lr], p0); atomicAdd(&sdot1[lr + 8], p1); }
                if (o2) { atomicAdd(&sdot2[lr], q0); atomicAdd(&sdot2[lr + 8], q1); }
            }
        }
        __syncthreads();
        if (tid < BM) {
            if (o1) o1[(bm + tid) * H_N + h] = sdot1[tid];
            if (o2) o2[(bm + tid) * H_N + h] = sdot2[tid];
        }
    }
}

// ---------------------------------------------------------------------------
// Merged aggregation, warp-parallel attention:
// lane j holds edge j of a 32-edge chunk in registers (coalesced ci load +
// parallel el gather); softmax max/sum via shuffle reductions; z accumulation
// loop unrolled x4 with broadcast indices -> high MLP.
// ---------------------------------------------------------------------------
__global__ __launch_bounds__(128) void k_agg2(
    const int* __restrict__ beg_ww, const int* __restrict__ deg_ww,
    const int* __restrict__ ci_ww,
    const float* __restrict__ z_ww, const float* __restrict__ el_ww,
    const float* __restrict__ er_ww, const float* __restrict__ b_ww,
    float* __restrict__ out_ww,
    const int* __restrict__ beg_wd, const int* __restrict__ deg_wd,
    const int* __restrict__ ci_wd,
    const float* __restrict__ z_wd, const float* __restrict__ el_wd,
    const float* __restrict__ er_wd, const float* __restrict__ b_wd,
    float* __restrict__ out_wd,
    int round_out) {
    int nb = blockIdx.x;
    const int *begp, *degp, *ci;
    const float *z, *el, *er, *bias;
    float* out;
    int node;
    if (nb < N_W) {
        node = nb;
        begp = beg_ww; degp = deg_ww; ci = ci_ww;
        z = z_ww; el = el_ww; er = er_ww; bias = b_ww; out = out_ww;
    } else {
        node = nb - N_W;
        begp = beg_wd; degp = deg_wd; ci = ci_wd;
        z = z_wd; el = el_wd; er = er_wd; bias = b_wd; out = out_wd;
    }

    int t = threadIdx.x;
    int h = t >> 5, lane = t & 31;
    int col = h * F_OUT + lane * 4;

    int beg = begp[node];
    int deg = degp[node];
    float erh = er[node * H_N + h];

    float4 acc = make_float4(0.f, 0.f, 0.f, 0.f);
    float ssum = 0.f;
    const unsigned FULL = 0xffffffffu;

    if (deg > 0) {
        if (deg <= 32) {
            // edges resident in registers across the warp
            int s_l = 0;
            float e_l = -3.0e38f;
            if (lane < deg) {
                s_l = ci[beg + lane];                       // coalesced
                float e = el[s_l * H_N + h] + erh;          // parallel gather
                e_l = (e > 0.f) ? e : 0.2f * e;
            }
            float m = e_l;
            #pragma unroll
            for (int off = 16; off > 0; off >>= 1)
                m = fmaxf(m, __shfl_xor_sync(FULL, m, off));
            float w_l = (lane < deg) ? __expf(e_l - m) : 0.f;
            float ws = w_l;
            #pragma unroll
            for (int off = 16; off > 0; off >>= 1)
                ws += __shfl_xor_sync(FULL, ws, off);
            ssum = ws;

            int j = 0;
            for (; j + 4 <= deg; j += 4) {
                int s0 = __shfl_sync(FULL, s_l, j);
                int s1 = __shfl_sync(FULL, s_l, j + 1);
                int s2 = __shfl_sync(FULL, s_l, j + 2);
                int s3 = __shfl_sync(FULL, s_l, j + 3);
                float w0 = __shfl_sync(FULL, w_l, j);
                float w1 = __shfl_sync(FULL, w_l, j + 1);
                float w2 = __shfl_sync(FULL, w_l, j + 2);
                float w3 = __shfl_sync(FULL, w_l, j + 3);
                float4 z0 = *(const float4*)(z + (size_t)s0 * HF + col);
                float4 z1 = *(const float4*)(z + (size_t)s1 * HF + col);
                float4 z2 = *(const float4*)(z + (size_t)s2 * HF + col);
                float4 z3 = *(const float4*)(z + (size_t)s3 * HF + col);
                acc.x += w0 * z0.x; acc.y += w0 * z0.y; acc.z += w0 * z0.z; acc.w += w0 * z0.w;
                acc.x += w1 * z1.x; acc.y += w1 * z1.y; acc.z += w1 * z1.z; acc.w += w1 * z1.w;
                acc.x += w2 * z2.x; acc.y += w2 * z2.y; acc.z += w2 * z2.z; acc.w += w2 * z2.w;
                acc.x += w3 * z3.x; acc.y += w3 * z3.y; acc.z += w3 * z3.z; acc.w += w3 * z3.w;
            }
            for (; j < deg; j++) {
                int s0 = __shfl_sync(FULL, s_l, j);
                float w0 = __shfl_sync(FULL, w_l, j);
                float4 z0 = *(const float4*)(z + (size_t)s0 * HF + col);
                acc.x += w0 * z0.x; acc.y += w0 * z0.y; acc.z += w0 * z0.z; acc.w += w0 * z0.w;
            }
        } else {
            // chunked fallback (rare: deg > 32)
            float m = -3.0e38f;
            for (int c = 0; c < deg; c += 32) {
                int j = c + lane;
                float e_l = -3.0e38f;
                if (j < deg) {
                    int s = ci[beg + j];
                    float e = el[s * H_N + h] + erh;
                    e_l = (e > 0.f) ? e : 0.2f * e;
                }
                m = fmaxf(m, e_l);
            }
            #pragma unroll
            for (int off = 16; off > 0; off >>= 1)
                m = fmaxf(m, __shfl_xor_sync(FULL, m, off));

            for (int c = 0; c < deg; c += 32) {
                int j = c + lane;
                int s_l = 0;
                float w_l = 0.f;
                if (j < deg) {
                    s_l = ci[beg + j];
                    float e = el[s_l * H_N + h] + erh;
                    e = (e > 0.f) ? e : 0.2f * e;
                    w_l = __expf(e - m);
                }
                float ws = w_l;
                #pragma unroll
                for (int off = 16; off > 0; off >>= 1)
                    ws += __shfl_xor_sync(FULL, ws, off);
                ssum += ws;

                int cnt = deg - c; if (cnt > 32) cnt = 32;
                int jj = 0;
                for (; jj + 2 <= cnt; jj += 2) {
                    int s0 = __shfl_sync(FULL, s_l, jj);
                    int s1 = __shfl_sync(FULL, s_l, jj + 1);
                    float w0 = __shfl_sync(FULL, w_l, jj);
                    float w1 = __shfl_sync(FULL, w_l, jj + 1);
                    float4 z0 = *(const float4*)(z + (size_t)s0 * HF + col);
                    float4 z1 = *(const float4*)(z + (size_t)s1 * HF + col);
                    acc.x += w0 * z0.x; acc.y += w0 * z0.y; acc.z += w0 * z0.z; acc.w += w0 * z0.w;
                    acc.x += w1 * z1.x; acc.y += w1 * z1.y; acc.z += w1 * z1.z; acc.w += w1 * z1.w;
                }
                for (; jj < cnt; jj++) {
                    int s0 = __shfl_sync(FULL, s_l, jj);
                    float w0 = __shfl_sync(FULL, w_l, jj);
                    float4 z0 = *(const float4*)(z + (size_t)s0 * HF + col);
                    acc.x += w0 * z0.x; acc.y += w0 * z0.y; acc.z += w0 * z0.z; acc.w += w0 * z0.w;
                }
            }
        }
    }

    float4 bv = *(const float4*)(bias + col);
    float4 o;
    if (deg > 0) {
        float inv = 1.f / ssum;
        o = make_float4(acc.x * inv + bv.x, acc.y * inv + bv.y,
                        acc.z * inv + bv.z, acc.w * inv + bv.w);
    } else {
        o = bv;
    }

    __shared__ float sm[HF];
    *(float4*)(&sm[col]) = o;
    __syncthreads();
    float r = sm[t] + sm[128 + t] + sm[256 + t] + sm[384 + t];
    r = fmaxf(r, 0.f);
    if (round_out) r = roundtf(r);
    out[(size_t)node * F_OUT + t] = r;
}

// ---------------------------------------------------------------------------
// Host launch
// ---------------------------------------------------------------------------
extern "C" void kernel_launch(void* const* d_in, const int* in_sizes, int n_in,
                              void* d_out, int out_size) {
    const float* x_word = (const float*)d_in[0];
    const float* x_doc  = (const float*)d_in[1];
    const float* W_ww0  = (const float*)d_in[2];
    const float* al_ww0 = (const float*)d_in[3];
    const float* ar_ww0 = (const float*)d_in[4];
    const float* b_ww0  = (const float*)d_in[5];
    const float* W_wd0  = (const float*)d_in[6];
    const float* al_wd0 = (const float*)d_in[7];
    const float* ar_wd0 = (const float*)d_in[8];
    const float* b_wd0  = (const float*)d_in[9];
    const float* W_ww1  = (const float*)d_in[10];
    const float* al_ww1 = (const float*)d_in[11];
    const float* ar_ww1 = (const float*)d_in[12];
    const float* b_ww1  = (const float*)d_in[13];
    const float* W_wd1  = (const float*)d_in[14];
    const float* al_wd1 = (const float*)d_in[15];
    const float* ar_wd1 = (const float*)d_in[16];
    const float* b_wd1  = (const float*)d_in[17];
    const int* ww_src = (const int*)d_in[18];
    const int* ww_dst = (const int*)d_in[19];
    const int* wd_src = (const int*)d_in[20];
    const int* wd_dst = (const int*)d_in[21];

    float* out = (float*)d_out;

    float *z_ww, *z_wd, *zd_wd, *el_ww, *er_ww, *el_wd, *er_wd, *xw1, *xd1;
    float *xw_r, *xd_r, *w0a, *w0b, *w1a, *w1b;
    int *deg_ww, *deg_wd, *beg_ww, *beg_wd, *cur_ww, *cur_wd, *ci_ww, *ci_wd, *total;
    cudaGetSymbolAddress((void**)&z_ww, g_z_ww);
    cudaGetSymbolAddress((void**)&z_wd, g_z_wd);
    cudaGetSymbolAddress((void**)&zd_wd, g_zd_wd);
    cudaGetSymbolAddress((void**)&el_ww, g_el_ww);
    cudaGetSymbolAddress((void**)&er_ww, g_er_ww);
    cudaGetSymbolAddress((void**)&el_wd, g_el_wd);
    cudaGetSymbolAddress((void**)&er_wd, g_er_wd);
    cudaGetSymbolAddress((void**)&xw1, g_xw1);
    cudaGetSymbolAddress((void**)&xd1, g_xd1);
    cudaGetSymbolAddress((void**)&xw_r, g_xw_r);
    cudaGetSymbolAddress((void**)&xd_r, g_xd_r);
    cudaGetSymbolAddress((void**)&w0a, g_w0a);
    cudaGetSymbolAddress((void**)&w0b, g_w0b);
    cudaGetSymbolAddress((void**)&w1a, g_w1a);
    cudaGetSymbolAddress((void**)&w1b, g_w1b);
    cudaGetSymbolAddress((void**)&deg_ww, g_deg_ww);
    cudaGetSymbolAddress((void**)&deg_wd, g_deg_wd);
    cudaGetSymbolAddress((void**)&beg_ww, g_beg_ww);
    cudaGetSymbolAddress((void**)&beg_wd, g_beg_wd);
    cudaGetSymbolAddress((void**)&cur_ww, g_cur_ww);
    cudaGetSymbolAddress((void**)&cur_wd, g_cur_wd);
    cudaGetSymbolAddress((void**)&ci_ww, g_ci_ww);
    cudaGetSymbolAddress((void**)&ci_wd, g_ci_wd);
    cudaGetSymbolAddress((void**)&total, g_total);

    cudaFuncSetAttribute(k_gemm3, cudaFuncAttributeMaxDynamicSharedMemorySize, DYN_SMEM);

    const int TB = 256;
    const int TW = N_W / BM;   // 625
    const int TD = N_D / BM;   // 125

    // ---- 0,1: round x inputs; 2: round all 4 W mats ----
    {
        int n4w = N_W * 256 / 4;
        k_round<<<(n4w + TB - 1) / TB, TB>>>((const float4*)x_word, (float4*)xw_r, n4w);
        int n4d = N_D * 256 / 4;
        k_round<<<(n4d + TB - 1) / TB, TB>>>((const float4*)x_doc, (float4*)xd_r, n4d);
        int a = 256 * 512 / 4, bsz = 128 * 512 / 4;
        int tot = a + a + bsz + bsz;
        k_round4<<<(tot + TB - 1) / TB, TB>>>(
            (const float4*)W_ww0, (float4*)w0a, a,
            (const float4*)W_wd0, (float4*)w0b, a,
            (const float4*)W_ww1, (float4*)w1a, bsz,
            (const float4*)W_wd1, (float4*)w1b, bsz);
    }

    // ---- 3: merged L0 GEMMs (profiled launch index 3) ----
    k_gemm3<<<dim3(4, TW + TW + TD), 512, DYN_SMEM>>>(
        xw_r, w0a, z_ww, al_ww0, ar_ww0, el_ww, er_ww, TW,
        xw_r, w0b, z_wd, al_wd0, nullptr, el_wd, nullptr, TW,
        xd_r, w0b, zd_wd, nullptr, ar_wd0, nullptr, er_wd,
        256);

    // ---- merged CSR ----
    k_zero_multi<<<(N_W + N_D + N_W + N_D + 2 + TB - 1) / TB, TB>>>(
        deg_ww, N_W, deg_wd, N_D, cur_ww, N_W, cur_wd, N_D, total, 2);
    k_hist2<<<(E_WW + E_WD + TB - 1) / TB, TB>>>(ww_dst, wd_dst, deg_ww, deg_wd);
    k_offsets2<<<(N_W + N_D + TB - 1) / TB, TB>>>(deg_ww, beg_ww, deg_wd, beg_wd, total);
    k_scatter2<<<(E_WW + E_WD + TB - 1) / TB, TB>>>(
        ww_src, ww_dst, wd_src, wd_dst,
        beg_ww, cur_ww, ci_ww, beg_wd, cur_wd, ci_wd);

    // ---- merged L0 aggregation (outputs tf32-rounded) ----
    k_agg2<<<N_W + N_D, 128>>>(
        beg_ww, deg_ww, ci_ww, z_ww, el_ww, er_ww, b_ww0, xw1,
        beg_wd, deg_wd, ci_wd, z_wd, el_wd, er_wd, b_wd0, xd1, 1);

    // ---- merged L1 GEMMs ----
    k_gemm3<<<dim3(4, TW + TW + TD), 512, DYN_SMEM>>>(
        xw1, w1a, z_ww, al_ww1, ar_ww1, el_ww, er_ww, TW,
        xw1, w1b, z_wd, al_wd1, nullptr, el_wd, nullptr, TW,
        xd1, w1b, zd_wd, nullptr, ar_wd1, nullptr, er_wd,
        128);

    // ---- merged L1 aggregation -> output ----
    k_agg2<<<N_W + N_D, 128>>>(
        beg_ww, deg_ww, ci_ww, z_ww, el_ww, er_ww, b_ww1, out,
        beg_wd, deg_wd, ci_wd, z_wd, el_wd, er_wd, b_wd1,
        out + (size_t)N_W * F_OUT, 0);
}

// round 15
// speedup vs baseline: 1.1524x; 1.1524x over previous
#include <cuda_runtime.h>
#include <cuda_fp16.h>
#include <math.h>
#include <stdint.h>

// Problem constants
#define N_W   80000
#define N_D   16000
#define E_WW  200000
#define E_WD  200000
#define HF    512      // H*F = 4*128
#define F_OUT 128
#define H_N   4

// GEMM tiling (fp16, m16n8k16)
#define BM 128
#define BN 128
#define BK 32
#define NSTAGE 4
#define ST_H 40                         // halfs per smem row (32 + 8 pad), 80B (16B mult)
#define A_TILE_H (BM * ST_H)            // halfs per A stage
#define B_TILE_H (BN * ST_H)            // halfs per B stage
#define DYN_SMEM ((NSTAGE * (A_TILE_H + B_TILE_H)) * 2)   // 81920 bytes

// ---------------------------------------------------------------------------
// Static device scratch (allocation-free rule)
// ---------------------------------------------------------------------------
__device__ float  g_z_ww[(size_t)N_W * HF];
__device__ float  g_z_wd[(size_t)N_W * HF];
__device__ float  g_zd_wd[(size_t)N_D * HF];
__device__ float  g_el_ww[N_W * H_N];
__device__ float  g_er_ww[N_W * H_N];
__device__ float  g_el_wd[N_W * H_N];
__device__ float  g_er_wd[N_D * H_N];
__device__ __half g_xw_h[(size_t)N_W * 256];   // fp16 x_word
__device__ __half g_xd_h[(size_t)N_D * 256];   // fp16 x_doc
__device__ __half g_xw1h[(size_t)N_W * F_OUT]; // fp16 layer-0 word out
__device__ __half g_xd1h[(size_t)N_D * F_OUT]; // fp16 layer-0 doc out
__device__ __half g_wt0a[512 * 256];           // W_ww0^T [N][K] fp16
__device__ __half g_wt0b[512 * 256];           // W_wd0^T
__device__ __half g_wt1a[512 * 128];           // W_ww1^T
__device__ __half g_wt1b[512 * 128];           // W_wd1^T
__device__ int    g_deg_ww[N_W];
__device__ int    g_deg_wd[N_D];
__device__ int    g_beg_ww[N_W];
__device__ int    g_beg_wd[N_D];
__device__ int    g_cur_ww[N_W];
__device__ int    g_cur_wd[N_D];
__device__ int    g_ci_ww[E_WW];
__device__ int    g_ci_wd[E_WD];
__device__ int    g_total[2];

// ---------------------------------------------------------------------------
// helpers
// ---------------------------------------------------------------------------
__device__ __forceinline__ void cpa16(uint32_t dst, const void* src) {
    asm volatile("cp.async.cg.shared.global [%0], [%1], 16;" :: "r"(dst), "l"(src));
}
__device__ __forceinline__ void cp_commit() {
    asm volatile("cp.async.commit_group;");
}
__device__ __forceinline__ void mma_f16(float* d, const uint32_t* a, const uint32_t* b) {
    asm volatile(
        "mma.sync.aligned.m16n8k16.row.col.f32.f16.f16.f32 "
        "{%0,%1,%2,%3}, {%4,%5,%6,%7}, {%8,%9}, {%0,%1,%2,%3};\n"
        : "+f"(d[0]), "+f"(d[1]), "+f"(d[2]), "+f"(d[3])
        : "r"(a[0]), "r"(a[1]), "r"(a[2]), "r"(a[3]), "r"(b[0]), "r"(b[1]));
}

// ---------------------------------------------------------------------------
// fp16 conversion kernels
// ---------------------------------------------------------------------------
// f32[n] -> half[n], 8 elems/thread
__global__ void k_tohalf(const float4* __restrict__ src, uint4* __restrict__ dst, int n8) {
    int i = blockIdx.x * blockDim.x + threadIdx.x;
    if (i < n8) {
        float4 a = src[2 * i], b = src[2 * i + 1];
        __half2 h0 = __floats2half2_rn(a.x, a.y);
        __half2 h1 = __floats2half2_rn(a.z, a.w);
        __half2 h2 = __floats2half2_rn(b.x, b.y);
        __half2 h3 = __floats2half2_rn(b.z, b.w);
        uint4 v;
        v.x = *(uint32_t*)&h0; v.y = *(uint32_t*)&h1;
        v.z = *(uint32_t*)&h2; v.w = *(uint32_t*)&h3;
        dst[i] = v;
    }
}

// 4 W mats [K][512] f32 -> WT [512][K] half, one launch
__global__ void k_toT4(const float* s0, __half* d0, int k0,
                       const float* s1, __half* d1, int k1,
                       const float* s2, __half* d2, int k2,
                       const float* s3, __half* d3, int k3) {
    int i = blockIdx.x * blockDim.x + threadIdx.x;
    const float* s; __half* d; int K; int j = i;
    if (j < k0 * 512) { s = s0; d = d0; K = k0; }
    else { j -= k0 * 512;
        if (j < k1 * 512) { s = s1; d = d1; K = k1; }
        else { j -= k1 * 512;
            if (j < k2 * 512) { s = s2; d = d2; K = k2; }
            else { j -= k2 * 512;
                if (j < k3 * 512) { s = s3; d = d3; K = k3; }
                else return;
            }
        }
    }
    int k = j >> 9;          // j / 512
    int n = j & 511;
    d[n * K + k] = __float2half_rn(s[j]);
}

// ---------------------------------------------------------------------------
// Merged CSR build
// ---------------------------------------------------------------------------
__global__ void k_zero_multi(int* p0, int n0, int* p1, int n1,
                             int* p2, int n2, int* p3, int n3,
                             int* p4, int n4) {
    int i = blockIdx.x * blockDim.x + threadIdx.x;
    int* p; int j = i;
    if (j < n0) p = p0;
    else { j -= n0;
        if (j < n1) p = p1;
        else { j -= n1;
            if (j < n2) p = p2;
            else { j -= n2;
                if (j < n3) p = p3;
                else { j -= n3;
                    if (j < n4) p = p4;
                    else return;
                }
            }
        }
    }
    p[j] = 0;
}

__global__ void k_hist2(const int* __restrict__ dst_ww, const int* __restrict__ dst_wd,
                        int* __restrict__ deg_ww, int* __restrict__ deg_wd) {
    int i = blockIdx.x * blockDim.x + threadIdx.x;
    if (i < E_WW) atomicAdd(&deg_ww[dst_ww[i]], 1);
    else if (i < E_WW + E_WD) atomicAdd(&deg_wd[dst_wd[i - E_WW]], 1);
}

__global__ void k_offsets2(const int* __restrict__ deg_ww, int* __restrict__ beg_ww,
                           const int* __restrict__ deg_wd, int* __restrict__ beg_wd,
                           int* __restrict__ total) {
    int i = blockIdx.x * blockDim.x + threadIdx.x;
    int lane = threadIdx.x & 31;
    const int* deg; int* beg; int* tot; int j; bool ok = true;
    if (i < N_W) { deg = deg_ww; beg = beg_ww; tot = total; j = i; }
    else if (i < N_W + N_D) { deg = deg_wd; beg = beg_wd; tot = total + 1; j = i - N_W; }
    else ok = false;
    int v = ok ? deg[j] : 0;
    int s = v;
    #pragma unroll
    for (int off = 1; off < 32; off <<= 1) {
        int t = __shfl_up_sync(0xffffffffu, s, off);
        if (lane >= off) s += t;
    }
    int wtot = __shfl_sync(0xffffffffu, s, 31);
    int base = 0;
    if (lane == 31 && ok) base = atomicAdd(tot, wtot);
    base = __shfl_sync(0xffffffffu, base, 31);
    if (ok) beg[j] = base + s - v;
}

__global__ void k_scatter2(const int* __restrict__ ww_src, const int* __restrict__ ww_dst,
                           const int* __restrict__ wd_src, const int* __restrict__ wd_dst,
                           const int* __restrict__ beg_ww, int* __restrict__ cur_ww,
                           int* __restrict__ ci_ww,
                           const int* __restrict__ beg_wd, int* __restrict__ cur_wd,
                           int* __restrict__ ci_wd) {
    int i = blockIdx.x * blockDim.x + threadIdx.x;
    if (i < E_WW) {
        int d = ww_dst[i];
        int p = atomicAdd(&cur_ww[d], 1);
        ci_ww[beg_ww[d] + p] = ww_src[i];
    } else if (i < E_WW + E_WD) {
        int j = i - E_WW;
        int d = wd_dst[j];
        int p = atomicAdd(&cur_wd[d], 1);
        ci_wd[beg_wd[d] + p] = wd_src[j];
    }
}

// ---------------------------------------------------------------------------
// FP16 tensor-core GEMM (3 segments / launch): C[M,512] = A[M,K] @ WT[512,K]^T
// 128x128 tile, 512 threads (16 warps, 4m x 4n, warptile 32x32),
// mma.m16n8k16.f16 (f32 accum), BK=32, 4-stage cp.async, 1 barrier/iter.
// Fused per-head attention-dot epilogue (f32).
// ---------------------------------------------------------------------------
__global__ __launch_bounds__(512, 2) void k_gemm3(
    const __half* __restrict__ A0, const __half* __restrict__ B0, float* __restrict__ C0,
    const float* __restrict__ v10, const float* __restrict__ v20,
    float* __restrict__ o10, float* __restrict__ o20, int t0,
    const __half* __restrict__ A1, const __half* __restrict__ B1, float* __restrict__ C1,
    const float* __restrict__ v11, const float* __restrict__ v21,
    float* __restrict__ o11, float* __restrict__ o21, int t1,
    const __half* __restrict__ A2, const __half* __restrict__ B2, float* __restrict__ C2,
    const float* __restrict__ v12, const float* __restrict__ v22,
    float* __restrict__ o12, float* __restrict__ o22,
    int K) {
    extern __shared__ __align__(16) __half hsm[];
    __shared__ float sdot1[BM];
    __shared__ float sdot2[BM];

    __half* AsBase = hsm;                         // NSTAGE * A_TILE_H
    __half* BsBase = hsm + NSTAGE * A_TILE_H;     // NSTAGE * B_TILE_H

    int by = blockIdx.y;
    const __half *A, *Bt;
    const float *v1, *v2;
    float *C, *o1, *o2;
    if (by < t0) { A = A0; Bt = B0; C = C0; v1 = v10; v2 = v20; o1 = o10; o2 = o20; }
    else if (by < t0 + t1) { by -= t0; A = A1; Bt = B1; C = C1; v1 = v11; v2 = v21; o1 = o11; o2 = o21; }
    else { by -= t0 + t1; A = A2; Bt = B2; C = C2; v1 = v12; v2 = v22; o1 = o12; o2 = o22; }

    int tid = threadIdx.x;
    int lane = tid & 31, wid = tid >> 5;
    int g = lane >> 2, t4 = lane & 3;
    int wm = wid & 3, wn = wid >> 2;
    int bm = by * BM;
    int h  = blockIdx.x;
    int bn = h * BN;

    if (tid < BM) { sdot1[tid] = 0.f; sdot2[tid] = 0.f; }

    // staging: one 16B chunk per thread for A and for B per stage
    int s_row = tid >> 2;            // 0..127
    int s_ch  = (tid & 3) * 8;       // half offset 0,8,16,24

    const __half* Ap = A + (size_t)bm * K;
    const __half* Bp = Bt + (size_t)bn * K;

    uint32_t as_base = (uint32_t)__cvta_generic_to_shared(AsBase);
    uint32_t bs_base = (uint32_t)__cvta_generic_to_shared(BsBase);
    const uint32_t A_BUF = A_TILE_H * 2;
    const uint32_t B_BUF = B_TILE_H * 2;

    float acc[2][4][4] = {};

    int nk = K / BK;

    #pragma unroll
    for (int st = 0; st < NSTAGE - 1; st++) {
        int k0 = st * BK;
        cpa16(as_base + st * A_BUF + (s_row * ST_H + s_ch) * 2,
              Ap + (size_t)s_row * K + k0 + s_ch);
        cpa16(bs_base + st * B_BUF + (s_row * ST_H + s_ch) * 2,
              Bp + (size_t)s_row * K + k0 + s_ch);
        cp_commit();
    }

    for (int kt = 0; kt < nk; kt++) {
        int st = kt & (NSTAGE - 1);
        asm volatile("cp.async.wait_group %0;" :: "n"(NSTAGE - 2));
        __syncthreads();

        if (kt + NSTAGE - 1 < nk) {
            int kf = kt + NSTAGE - 1;
            int stn = kf & (NSTAGE - 1);
            int k0 = kf * BK;
            cpa16(as_base + stn * A_BUF + (s_row * ST_H + s_ch) * 2,
                  Ap + (size_t)s_row * K + k0 + s_ch);
            cpa16(bs_base + stn * B_BUF + (s_row * ST_H + s_ch) * 2,
                  Bp + (size_t)s_row * K + k0 + s_ch);
        }
        cp_commit();

        const __half* As_st = AsBase + st * A_TILE_H;
        const __half* Bs_st = BsBase + st * B_TILE_H;

        #pragma unroll
        for (int s = 0; s < 2; s++) {            // two k16 steps per BK=32
            int kb = s * 16;
            uint32_t a[2][4], b[4][2];
            #pragma unroll
            for (int mi = 0; mi < 2; mi++) {
                int r = wm * 32 + mi * 16;
                a[mi][0] = *(const uint32_t*)&As_st[(r + g) * ST_H + kb + 2 * t4];
                a[mi][1] = *(const uint32_t*)&As_st[(r + 8 + g) * ST_H + kb + 2 * t4];
                a[mi][2] = *(const uint32_t*)&As_st[(r + g) * ST_H + kb + 2 * t4 + 8];
                a[mi][3] = *(const uint32_t*)&As_st[(r + 8 + g) * ST_H + kb + 2 * t4 + 8];
            }
            #pragma unroll
            for (int nj = 0; nj < 4; nj++) {
                int c = wn * 32 + nj * 8 + g;
                b[nj][0] = *(const uint32_t*)&Bs_st[c * ST_H + kb + 2 * t4];
                b[nj][1] = *(const uint32_t*)&Bs_st[c * ST_H + kb + 2 * t4 + 8];
            }
            #pragma unroll
            for (int mi = 0; mi < 2; mi++)
                #pragma unroll
                for (int nj = 0; nj < 4; nj++)
                    mma_f16(acc[mi][nj], a[mi], b[nj]);
        }
    }

    #pragma unroll
    for (int mi = 0; mi < 2; mi++) {
        int r0 = bm + wm * 32 + mi * 16 + g;
        int r1 = r0 + 8;
        #pragma unroll
        for (int nj = 0; nj < 4; nj++) {
            int c = bn + wn * 32 + nj * 8 + 2 * t4;
            *(float2*)(C + (size_t)r0 * 512 + c) = make_float2(acc[mi][nj][0], acc[mi][nj][1]);
            *(float2*)(C + (size_t)r1 * 512 + c) = make_float2(acc[mi][nj][2], acc[mi][nj][3]);
        }
    }

    if (o1 || o2) {
        float w1v[4][2], w2v[4][2];
        #pragma unroll
        for (int nj = 0; nj < 4; nj++) {
            int c = wn * 32 + nj * 8 + 2 * t4;
            if (o1) { w1v[nj][0] = v1[h * 128 + c]; w1v[nj][1] = v1[h * 128 + c + 1]; }
            if (o2) { w2v[nj][0] = v2[h * 128 + c]; w2v[nj][1] = v2[h * 128 + c + 1]; }
        }
        #pragma unroll
        for (int mi = 0; mi < 2; mi++) {
            float p0 = 0.f, p1 = 0.f, q0 = 0.f, q1 = 0.f;
            #pragma unroll
            for (int nj = 0; nj < 4; nj++) {
                if (o1) {
                    p0 += acc[mi][nj][0] * w1v[nj][0] + acc[mi][nj][1] * w1v[nj][1];
                    p1 += acc[mi][nj][2] * w1v[nj][0] + acc[mi][nj][3] * w1v[nj][1];
                }
                if (o2) {
                    q0 += acc[mi][nj][0] * w2v[nj][0] + acc[mi][nj][1] * w2v[nj][1];
                    q1 += acc[mi][nj][2] * w2v[nj][0] + acc[mi][nj][3] * w2v[nj][1];
                }
            }
            p0 += __shfl_down_sync(0xffffffffu, p0, 2, 4);
            p0 += __shfl_down_sync(0xffffffffu, p0, 1, 4);
            p1 += __shfl_down_sync(0xffffffffu, p1, 2, 4);
            p1 += __shfl_down_sync(0xffffffffu, p1, 1, 4);
            q0 += __shfl_down_sync(0xffffffffu, q0, 2, 4);
            q0 += __shfl_down_sync(0xffffffffu, q0, 1, 4);
            q1 += __shfl_down_sync(0xffffffffu, q1, 2, 4);
            q1 += __shfl_down_sync(0xffffffffu, q1, 1, 4);
            if (t4 == 0) {
                int lr = wm * 32 + mi * 16 + g;
                if (o1) { atomicAdd(&sdot1[lr], p0); atomicAdd(&sdot1[lr + 8], p1); }
                if (o2) { atomicAdd(&sdot2[lr], q0); atomicAdd(&sdot2[lr + 8], q1); }
            }
        }
        __syncthreads();
        if (tid < BM) {
            if (o1) o1[(bm + tid) * H_N + h] = sdot1[tid];
            if (o2) o2[(bm + tid) * H_N + h] = sdot2[tid];
        }
    }
}

// ---------------------------------------------------------------------------
// Merged aggregation (round-13 serial two-pass — proven fastest):
// writes fp16 (intermediate layer) or f32 (final output).
// ---------------------------------------------------------------------------
__global__ __launch_bounds__(128) void k_agg2(
    const int* __restrict__ beg_ww, const int* __restrict__ deg_ww,
    const int* __restrict__ ci_ww,
    const float* __restrict__ z_ww, const float* __restrict__ el_ww,
    const float* __restrict__ er_ww, const float* __restrict__ b_ww,
    float* __restrict__ outf_ww, __half* __restrict__ outh_ww,
    const int* __restrict__ beg_wd, const int* __restrict__ deg_wd,
    const int* __restrict__ ci_wd,
    const float* __restrict__ z_wd, const float* __restrict__ el_wd,
    const float* __restrict__ er_wd, const float* __restrict__ b_wd,
    float* __restrict__ outf_wd, __half* __restrict__ outh_wd) {
    int nb = blockIdx.x;
    const int *begp, *degp, *ci;
    const float *z, *el, *er, *bias;
    float* outf; __half* outh;
    int node;
    if (nb < N_W) {
        node = nb;
        begp = beg_ww; degp = deg_ww; ci = ci_ww;
        z = z_ww; el = el_ww; er = er_ww; bias = b_ww;
        outf = outf_ww; outh = outh_ww;
    } else {
        node = nb - N_W;
        begp = beg_wd; degp = deg_wd; ci = ci_wd;
        z = z_wd; el = el_wd; er = er_wd; bias = b_wd;
        outf = outf_wd; outh = outh_wd;
    }

    int t = threadIdx.x;
    int h = t >> 5, lane = t & 31;
    int col = h * F_OUT + lane * 4;

    int beg = begp[node];
    int end = beg + degp[node];
    float erh = er[node * H_N + h];

    float m = -3.0e38f;
    for (int j = beg; j < end; j++) {
        int s = ci[j];
        float e = el[s * H_N + h] + erh;
        e = (e > 0.f) ? e : 0.2f * e;
        m = fmaxf(m, e);
    }

    float4 acc = make_float4(0.f, 0.f, 0.f, 0.f);
    float ssum = 0.f;
    for (int j = beg; j < end; j++) {
        int s = ci[j];
        float e = el[s * H_N + h] + erh;
        e = (e > 0.f) ? e : 0.2f * e;
        float w = __expf(e - m);
        float4 zv = *(const float4*)(z + (size_t)s * HF + col);
        acc.x += w * zv.x; acc.y += w * zv.y;
        acc.z += w * zv.z; acc.w += w * zv.w;
        ssum += w;
    }

    float4 bv = *(const float4*)(bias + col);
    float4 o;
    if (end > beg) {
        float inv = 1.f / ssum;
        o = make_float4(acc.x * inv + bv.x, acc.y * inv + bv.y,
                        acc.z * inv + bv.z, acc.w * inv + bv.w);
    } else {
        o = bv;
    }

    __shared__ float sm[HF];
    *(float4*)(&sm[col]) = o;
    __syncthreads();
    float r = sm[t] + sm[128 + t] + sm[256 + t] + sm[384 + t];
    r = fmaxf(r, 0.f);
    if (outh) outh[(size_t)node * F_OUT + t] = __float2half_rn(r);
    else      outf[(size_t)node * F_OUT + t] = r;
}

// ---------------------------------------------------------------------------
// Host launch
// ---------------------------------------------------------------------------
extern "C" void kernel_launch(void* const* d_in, const int* in_sizes, int n_in,
                              void* d_out, int out_size) {
    const float* x_word = (const float*)d_in[0];
    const float* x_doc  = (const float*)d_in[1];
    const float* W_ww0  = (const float*)d_in[2];
    const float* al_ww0 = (const float*)d_in[3];
    const float* ar_ww0 = (const float*)d_in[4];
    const float* b_ww0  = (const float*)d_in[5];
    const float* W_wd0  = (const float*)d_in[6];
    const float* al_wd0 = (const float*)d_in[7];
    const float* ar_wd0 = (const float*)d_in[8];
    const float* b_wd0  = (const float*)d_in[9];
    const float* W_ww1  = (const float*)d_in[10];
    const float* al_ww1 = (const float*)d_in[11];
    const float* ar_ww1 = (const float*)d_in[12];
    const float* b_ww1  = (const float*)d_in[13];
    const float* W_wd1  = (const float*)d_in[14];
    const float* al_wd1 = (const float*)d_in[15];
    const float* ar_wd1 = (const float*)d_in[16];
    const float* b_wd1  = (const float*)d_in[17];
    const int* ww_src = (const int*)d_in[18];
    const int* ww_dst = (const int*)d_in[19];
    const int* wd_src = (const int*)d_in[20];
    const int* wd_dst = (const int*)d_in[21];

    float* out = (float*)d_out;

    float *z_ww, *z_wd, *zd_wd, *el_ww, *er_ww, *el_wd, *er_wd;
    __half *xw_h, *xd_h, *xw1h, *xd1h, *wt0a, *wt0b, *wt1a, *wt1b;
    int *deg_ww, *deg_wd, *beg_ww, *beg_wd, *cur_ww, *cur_wd, *ci_ww, *ci_wd, *total;
    cudaGetSymbolAddress((void**)&z_ww, g_z_ww);
    cudaGetSymbolAddress((void**)&z_wd, g_z_wd);
    cudaGetSymbolAddress((void**)&zd_wd, g_zd_wd);
    cudaGetSymbolAddress((void**)&el_ww, g_el_ww);
    cudaGetSymbolAddress((void**)&er_ww, g_er_ww);
    cudaGetSymbolAddress((void**)&el_wd, g_el_wd);
    cudaGetSymbolAddress((void**)&er_wd, g_er_wd);
    cudaGetSymbolAddress((void**)&xw_h, g_xw_h);
    cudaGetSymbolAddress((void**)&xd_h, g_xd_h);
    cudaGetSymbolAddress((void**)&xw1h, g_xw1h);
    cudaGetSymbolAddress((void**)&xd1h, g_xd1h);
    cudaGetSymbolAddress((void**)&wt0a, g_wt0a);
    cudaGetSymbolAddress((void**)&wt0b, g_wt0b);
    cudaGetSymbolAddress((void**)&wt1a, g_wt1a);
    cudaGetSymbolAddress((void**)&wt1b, g_wt1b);
    cudaGetSymbolAddress((void**)&deg_ww, g_deg_ww);
    cudaGetSymbolAddress((void**)&deg_wd, g_deg_wd);
    cudaGetSymbolAddress((void**)&beg_ww, g_beg_ww);
    cudaGetSymbolAddress((void**)&beg_wd, g_beg_wd);
    cudaGetSymbolAddress((void**)&cur_ww, g_cur_ww);
    cudaGetSymbolAddress((void**)&cur_wd, g_cur_wd);
    cudaGetSymbolAddress((void**)&ci_ww, g_ci_ww);
    cudaGetSymbolAddress((void**)&ci_wd, g_ci_wd);
    cudaGetSymbolAddress((void**)&total, g_total);

    cudaFuncSetAttribute(k_gemm3, cudaFuncAttributeMaxDynamicSharedMemorySize, DYN_SMEM);

    const int TB = 256;
    const int TW = N_W / BM;   // 625
    const int TD = N_D / BM;   // 125

    // ---- 0,1: x inputs -> fp16; 2: all 4 W mats -> WT fp16 ----
    {
        int n8w = N_W * 256 / 8;
        k_tohalf<<<(n8w + TB - 1) / TB, TB>>>((const float4*)x_word, (uint4*)xw_h, n8w);
        int n8d = N_D * 256 / 8;
        k_tohalf<<<(n8d + TB - 1) / TB, TB>>>((const float4*)x_doc, (uint4*)xd_h, n8d);
        int tot = (256 + 256 + 128 + 128) * 512;
        k_toT4<<<(tot + TB - 1) / TB, TB>>>(
            W_ww0, wt0a, 256, W_wd0, wt0b, 256,
            W_ww1, wt1a, 128, W_wd1, wt1b, 128);
    }

    // ---- 3: merged L0 GEMMs (profiled launch index 3) ----
    k_gemm3<<<dim3(4, TW + TW + TD), 512, DYN_SMEM>>>(
        xw_h, wt0a, z_ww, al_ww0, ar_ww0, el_ww, er_ww, TW,
        xw_h, wt0b, z_wd, al_wd0, nullptr, el_wd, nullptr, TW,
        xd_h, wt0b, zd_wd, nullptr, ar_wd0, nullptr, er_wd,
        256);

    // ---- merged CSR ----
    k_zero_multi<<<(N_W + N_D + N_W + N_D + 2 + TB - 1) / TB, TB>>>(
        deg_ww, N_W, deg_wd, N_D, cur_ww, N_W, cur_wd, N_D, total, 2);
    k_hist2<<<(E_WW + E_WD + TB - 1) / TB, TB>>>(ww_dst, wd_dst, deg_ww, deg_wd);
    k_offsets2<<<(N_W + N_D + TB - 1) / TB, TB>>>(deg_ww, beg_ww, deg_wd, beg_wd, total);
    k_scatter2<<<(E_WW + E_WD + TB - 1) / TB, TB>>>(
        ww_src, ww_dst, wd_src, wd_dst,
        beg_ww, cur_ww, ci_ww, beg_wd, cur_wd, ci_wd);

    // ---- merged L0 aggregation -> fp16 intermediates ----
    k_agg2<<<N_W + N_D, 128>>>(
        beg_ww, deg_ww, ci_ww, z_ww, el_ww, er_ww, b_ww0, nullptr, xw1h,
        beg_wd, deg_wd, ci_wd, z_wd, el_wd, er_wd, b_wd0, nullptr, xd1h);

    // ---- merged L1 GEMMs ----
    k_gemm3<<<dim3(4, TW + TW + TD), 512, DYN_SMEM>>>(
        xw1h, wt1a, z_ww, al_ww1, ar_ww1, el_ww, er_ww, TW,
        xw1h, wt1b, z_wd, al_wd1, nullptr, el_wd, nullptr, TW,
        xd1h, wt1b, zd_wd, nullptr, ar_wd1, nullptr, er_wd,
        128);

    // ---- merged L1 aggregation -> f32 output ----
    k_agg2<<<N_W + N_D, 128>>>(
        beg_ww, deg_ww, ci_ww, z_ww, el_ww, er_ww, b_ww1, out, nullptr,
        beg_wd, deg_wd, ci_wd, z_wd, el_wd, er_wd, b_wd1,
        out + (size_t)N_W * F_OUT, nullptr);
}

// round 16
// speedup vs baseline: 1.3968x; 1.2121x over previous
#include <cuda_runtime.h>
#include <cuda_fp16.h>
#include <math.h>
#include <stdint.h>

// Problem constants
#define N_W   80000
#define N_D   16000
#define E_WW  200000
#define E_WD  200000
#define HF    512      // H*F = 4*128
#define F_OUT 128
#define H_N   4

// GEMM tiling (fp16, m16n8k16)
#define BM 128
#define BN 128
#define BK 32
#define NSTAGE 4
#define ST_H 40                         // halfs per smem row (32 + 8 pad)
#define A_TILE_H (BM * ST_H)
#define B_TILE_H (BN * ST_H)
#define DYN_SMEM ((NSTAGE * (A_TILE_H + B_TILE_H)) * 2)   // 81920 bytes

// ---------------------------------------------------------------------------
// Static device scratch (allocation-free rule)
// ---------------------------------------------------------------------------
__device__ __half g_z_ww[(size_t)N_W * HF];     // fp16 z
__device__ __half g_z_wd[(size_t)N_W * HF];
__device__ __half g_zd_wd[(size_t)N_D * HF];
__device__ float  g_el_ww[N_W * H_N];
__device__ float  g_er_ww[N_W * H_N];
__device__ float  g_el_wd[N_W * H_N];
__device__ float  g_er_wd[N_D * H_N];
__device__ __half g_xw_h[(size_t)N_W * 256];
__device__ __half g_xd_h[(size_t)N_D * 256];
__device__ __half g_xw1h[(size_t)N_W * F_OUT];
__device__ __half g_xd1h[(size_t)N_D * F_OUT];
__device__ __half g_wt0a[512 * 256];
__device__ __half g_wt0b[512 * 256];
__device__ __half g_wt1a[512 * 128];
__device__ __half g_wt1b[512 * 128];
__device__ int    g_deg_ww[N_W];
__device__ int    g_deg_wd[N_D];
__device__ int    g_beg_ww[N_W];
__device__ int    g_beg_wd[N_D];
__device__ int    g_cur_ww[N_W];
__device__ int    g_cur_wd[N_D];
__device__ int    g_ci_ww[E_WW];
__device__ int    g_ci_wd[E_WD];
__device__ int    g_total[2];

// ---------------------------------------------------------------------------
// helpers
// ---------------------------------------------------------------------------
__device__ __forceinline__ void cpa16(uint32_t dst, const void* src) {
    asm volatile("cp.async.cg.shared.global [%0], [%1], 16;" :: "r"(dst), "l"(src));
}
__device__ __forceinline__ void cp_commit() {
    asm volatile("cp.async.commit_group;");
}
__device__ __forceinline__ void mma_f16(float* d, const uint32_t* a, const uint32_t* b) {
    asm volatile(
        "mma.sync.aligned.m16n8k16.row.col.f32.f16.f16.f32 "
        "{%0,%1,%2,%3}, {%4,%5,%6,%7}, {%8,%9}, {%0,%1,%2,%3};\n"
        : "+f"(d[0]), "+f"(d[1]), "+f"(d[2]), "+f"(d[3])
        : "r"(a[0]), "r"(a[1]), "r"(a[2]), "r"(a[3]), "r"(b[0]), "r"(b[1]));
}
__device__ __forceinline__ void ldsm_x4(uint32_t& r0, uint32_t& r1, uint32_t& r2,
                                        uint32_t& r3, uint32_t addr) {
    asm volatile("ldmatrix.sync.aligned.m8n8.x4.shared.b16 {%0,%1,%2,%3}, [%4];"
        : "=r"(r0), "=r"(r1), "=r"(r2), "=r"(r3) : "r"(addr));
}

// ---------------------------------------------------------------------------
// fp16 conversion kernels
// ---------------------------------------------------------------------------
__global__ void k_tohalf(const float4* __restrict__ src, uint4* __restrict__ dst, int n8) {
    int i = blockIdx.x * blockDim.x + threadIdx.x;
    if (i < n8) {
        float4 a = src[2 * i], b = src[2 * i + 1];
        __half2 h0 = __floats2half2_rn(a.x, a.y);
        __half2 h1 = __floats2half2_rn(a.z, a.w);
        __half2 h2 = __floats2half2_rn(b.x, b.y);
        __half2 h3 = __floats2half2_rn(b.z, b.w);
        uint4 v;
        v.x = *(uint32_t*)&h0; v.y = *(uint32_t*)&h1;
        v.z = *(uint32_t*)&h2; v.w = *(uint32_t*)&h3;
        dst[i] = v;
    }
}

__global__ void k_toT4(const float* s0, __half* d0, int k0,
                       const float* s1, __half* d1, int k1,
                       const float* s2, __half* d2, int k2,
                       const float* s3, __half* d3, int k3) {
    int i = blockIdx.x * blockDim.x + threadIdx.x;
    const float* s; __half* d; int K; int j = i;
    if (j < k0 * 512) { s = s0; d = d0; K = k0; }
    else { j -= k0 * 512;
        if (j < k1 * 512) { s = s1; d = d1; K = k1; }
        else { j -= k1 * 512;
            if (j < k2 * 512) { s = s2; d = d2; K = k2; }
            else { j -= k2 * 512;
                if (j < k3 * 512) { s = s3; d = d3; K = k3; }
                else return;
            }
        }
    }
    int k = j >> 9;
    int n = j & 511;
    d[n * K + k] = __float2half_rn(s[j]);
}

// ---------------------------------------------------------------------------
// Merged CSR build
// ---------------------------------------------------------------------------
__global__ void k_zero_multi(int* p0, int n0, int* p1, int n1,
                             int* p2, int n2, int* p3, int n3,
                             int* p4, int n4) {
    int i = blockIdx.x * blockDim.x + threadIdx.x;
    int* p; int j = i;
    if (j < n0) p = p0;
    else { j -= n0;
        if (j < n1) p = p1;
        else { j -= n1;
            if (j < n2) p = p2;
            else { j -= n2;
                if (j < n3) p = p3;
                else { j -= n3;
                    if (j < n4) p = p4;
                    else return;
                }
            }
        }
    }
    p[j] = 0;
}

__global__ void k_hist2(const int* __restrict__ dst_ww, const int* __restrict__ dst_wd,
                        int* __restrict__ deg_ww, int* __restrict__ deg_wd) {
    int i = blockIdx.x * blockDim.x + threadIdx.x;
    if (i < E_WW) atomicAdd(&deg_ww[dst_ww[i]], 1);
    else if (i < E_WW + E_WD) atomicAdd(&deg_wd[dst_wd[i - E_WW]], 1);
}

__global__ void k_offsets2(const int* __restrict__ deg_ww, int* __restrict__ beg_ww,
                           const int* __restrict__ deg_wd, int* __restrict__ beg_wd,
                           int* __restrict__ total) {
    int i = blockIdx.x * blockDim.x + threadIdx.x;
    int lane = threadIdx.x & 31;
    const int* deg; int* beg; int* tot; int j; bool ok = true;
    if (i < N_W) { deg = deg_ww; beg = beg_ww; tot = total; j = i; }
    else if (i < N_W + N_D) { deg = deg_wd; beg = beg_wd; tot = total + 1; j = i - N_W; }
    else ok = false;
    int v = ok ? deg[j] : 0;
    int s = v;
    #pragma unroll
    for (int off = 1; off < 32; off <<= 1) {
        int t = __shfl_up_sync(0xffffffffu, s, off);
        if (lane >= off) s += t;
    }
    int wtot = __shfl_sync(0xffffffffu, s, 31);
    int base = 0;
    if (lane == 31 && ok) base = atomicAdd(tot, wtot);
    base = __shfl_sync(0xffffffffu, base, 31);
    if (ok) beg[j] = base + s - v;
}

__global__ void k_scatter2(const int* __restrict__ ww_src, const int* __restrict__ ww_dst,
                           const int* __restrict__ wd_src, const int* __restrict__ wd_dst,
                           const int* __restrict__ beg_ww, int* __restrict__ cur_ww,
                           int* __restrict__ ci_ww,
                           const int* __restrict__ beg_wd, int* __restrict__ cur_wd,
                           int* __restrict__ ci_wd) {
    int i = blockIdx.x * blockDim.x + threadIdx.x;
    if (i < E_WW) {
        int d = ww_dst[i];
        int p = atomicAdd(&cur_ww[d], 1);
        ci_ww[beg_ww[d] + p] = ww_src[i];
    } else if (i < E_WW + E_WD) {
        int j = i - E_WW;
        int d = wd_dst[j];
        int p = atomicAdd(&cur_wd[d], 1);
        ci_wd[beg_wd[d] + p] = wd_src[j];
    }
}

// ---------------------------------------------------------------------------
// FP16 tensor-core GEMM (3 segments / launch): Z[M,512] = A[M,K] @ WT[512,K]^T
// 128x128 tile, 512 threads (16 warps, 4m x 4n), mma.m16n8k16.f16 f32-accum,
// BK=32, 4-stage cp.async, ldmatrix.x4 fragment loads, fp16 Z store.
// Fused per-head attention-dot epilogue (from f32 accum).
// ---------------------------------------------------------------------------
__global__ __launch_bounds__(512, 2) void k_gemm3(
    const __half* __restrict__ A0, const __half* __restrict__ B0, __half* __restrict__ C0,
    const float* __restrict__ v10, const float* __restrict__ v20,
    float* __restrict__ o10, float* __restrict__ o20, int t0,
    const __half* __restrict__ A1, const __half* __restrict__ B1, __half* __restrict__ C1,
    const float* __restrict__ v11, const float* __restrict__ v21,
    float* __restrict__ o11, float* __restrict__ o21, int t1,
    const __half* __restrict__ A2, const __half* __restrict__ B2, __half* __restrict__ C2,
    const float* __restrict__ v12, const float* __restrict__ v22,
    float* __restrict__ o12, float* __restrict__ o22,
    int K) {
    extern __shared__ __align__(16) __half hsm[];
    __shared__ float sdot1[BM];
    __shared__ float sdot2[BM];

    __half* AsBase = hsm;
    __half* BsBase = hsm + NSTAGE * A_TILE_H;

    int by = blockIdx.y;
    const __half *A, *Bt;
    const float *v1, *v2;
    __half* C;
    float *o1, *o2;
    if (by < t0) { A = A0; Bt = B0; C = C0; v1 = v10; v2 = v20; o1 = o10; o2 = o20; }
    else if (by < t0 + t1) { by -= t0; A = A1; Bt = B1; C = C1; v1 = v11; v2 = v21; o1 = o11; o2 = o21; }
    else { by -= t0 + t1; A = A2; Bt = B2; C = C2; v1 = v12; v2 = v22; o1 = o12; o2 = o22; }

    int tid = threadIdx.x;
    int lane = tid & 31, wid = tid >> 5;
    int g = lane >> 2, t4 = lane & 3;
    int wm = wid & 3, wn = wid >> 2;
    int bm = by * BM;
    int h  = blockIdx.x;
    int bn = h * BN;

    if (tid < BM) { sdot1[tid] = 0.f; sdot2[tid] = 0.f; }

    // cp.async staging: one 16B chunk per thread per tile per stage
    int s_row = tid >> 2;
    int s_ch  = (tid & 3) * 8;

    const __half* Ap = A + (size_t)bm * K;
    const __half* Bp = Bt + (size_t)bn * K;

    uint32_t as_base = (uint32_t)__cvta_generic_to_shared(AsBase);
    uint32_t bs_base = (uint32_t)__cvta_generic_to_shared(BsBase);
    const uint32_t A_BUF = A_TILE_H * 2;
    const uint32_t B_BUF = B_TILE_H * 2;

    // ldmatrix per-lane half-offsets (add kb + stage base later)
    int lrow = lane & 7, sel = lane >> 3;
    int a_off[2], b_off[2];
    #pragma unroll
    for (int mi = 0; mi < 2; mi++)
        a_off[mi] = (wm * 32 + mi * 16 + (sel & 1) * 8 + lrow) * ST_H + (sel >> 1) * 8;
    #pragma unroll
    for (int njp = 0; njp < 2; njp++)
        b_off[njp] = (wn * 32 + (2 * njp + (sel >> 1)) * 8 + lrow) * ST_H + (sel & 1) * 8;

    float acc[2][4][4] = {};

    int nk = K / BK;

    #pragma unroll
    for (int st = 0; st < NSTAGE - 1; st++) {
        int k0 = st * BK;
        cpa16(as_base + st * A_BUF + (s_row * ST_H + s_ch) * 2,
              Ap + (size_t)s_row * K + k0 + s_ch);
        cpa16(bs_base + st * B_BUF + (s_row * ST_H + s_ch) * 2,
              Bp + (size_t)s_row * K + k0 + s_ch);
        cp_commit();
    }

    for (int kt = 0; kt < nk; kt++) {
        int st = kt & (NSTAGE - 1);
        asm volatile("cp.async.wait_group %0;" :: "n"(NSTAGE - 2));
        __syncthreads();

        if (kt + NSTAGE - 1 < nk) {
            int kf = kt + NSTAGE - 1;
            int stn = kf & (NSTAGE - 1);
            int k0 = kf * BK;
            cpa16(as_base + stn * A_BUF + (s_row * ST_H + s_ch) * 2,
                  Ap + (size_t)s_row * K + k0 + s_ch);
            cpa16(bs_base + stn * B_BUF + (s_row * ST_H + s_ch) * 2,
                  Bp + (size_t)s_row * K + k0 + s_ch);
        }
        cp_commit();

        uint32_t a_st = as_base + st * A_BUF;
        uint32_t b_st = bs_base + st * B_BUF;

        #pragma unroll
        for (int s = 0; s < 2; s++) {
            int kb = s * 16;
            uint32_t a[2][4], b[4][2];
            #pragma unroll
            for (int mi = 0; mi < 2; mi++)
                ldsm_x4(a[mi][0], a[mi][1], a[mi][2], a[mi][3],
                        a_st + (a_off[mi] + kb) * 2);
            #pragma unroll
            for (int njp = 0; njp < 2; njp++)
                ldsm_x4(b[2 * njp][0], b[2 * njp][1], b[2 * njp + 1][0], b[2 * njp + 1][1],
                        b_st + (b_off[njp] + kb) * 2);
            #pragma unroll
            for (int mi = 0; mi < 2; mi++)
                #pragma unroll
                for (int nj = 0; nj < 4; nj++)
                    mma_f16(acc[mi][nj], a[mi], b[nj]);
        }
    }

    // fp16 Z store
    #pragma unroll
    for (int mi = 0; mi < 2; mi++) {
        int r0 = bm + wm * 32 + mi * 16 + g;
        int r1 = r0 + 8;
        #pragma unroll
        for (int nj = 0; nj < 4; nj++) {
            int c = bn + wn * 32 + nj * 8 + 2 * t4;
            __half2 h0 = __floats2half2_rn(acc[mi][nj][0], acc[mi][nj][1]);
            __half2 h1 = __floats2half2_rn(acc[mi][nj][2], acc[mi][nj][3]);
            *(uint32_t*)(C + (size_t)r0 * 512 + c) = *(uint32_t*)&h0;
            *(uint32_t*)(C + (size_t)r1 * 512 + c) = *(uint32_t*)&h1;
        }
    }

    if (o1 || o2) {
        float w1v[4][2], w2v[4][2];
        #pragma unroll
        for (int nj = 0; nj < 4; nj++) {
            int c = wn * 32 + nj * 8 + 2 * t4;
            if (o1) { w1v[nj][0] = v1[h * 128 + c]; w1v[nj][1] = v1[h * 128 + c + 1]; }
            if (o2) { w2v[nj][0] = v2[h * 128 + c]; w2v[nj][1] = v2[h * 128 + c + 1]; }
        }
        #pragma unroll
        for (int mi = 0; mi < 2; mi++) {
            float p0 = 0.f, p1 = 0.f, q0 = 0.f, q1 = 0.f;
            #pragma unroll
            for (int nj = 0; nj < 4; nj++) {
                if (o1) {
                    p0 += acc[mi][nj][0] * w1v[nj][0] + acc[mi][nj][1] * w1v[nj][1];
                    p1 += acc[mi][nj][2] * w1v[nj][0] + acc[mi][nj][3] * w1v[nj][1];
                }
                if (o2) {
                    q0 += acc[mi][nj][0] * w2v[nj][0] + acc[mi][nj][1] * w2v[nj][1];
                    q1 += acc[mi][nj][2] * w2v[nj][0] + acc[mi][nj][3] * w2v[nj][1];
                }
            }
            p0 += __shfl_down_sync(0xffffffffu, p0, 2, 4);
            p0 += __shfl_down_sync(0xffffffffu, p0, 1, 4);
            p1 += __shfl_down_sync(0xffffffffu, p1, 2, 4);
            p1 += __shfl_down_sync(0xffffffffu, p1, 1, 4);
            q0 += __shfl_down_sync(0xffffffffu, q0, 2, 4);
            q0 += __shfl_down_sync(0xffffffffu, q0, 1, 4);
            q1 += __shfl_down_sync(0xffffffffu, q1, 2, 4);
            q1 += __shfl_down_sync(0xffffffffu, q1, 1, 4);
            if (t4 == 0) {
                int lr = wm * 32 + mi * 16 + g;
                if (o1) { atomicAdd(&sdot1[lr], p0); atomicAdd(&sdot1[lr + 8], p1); }
                if (o2) { atomicAdd(&sdot2[lr], q0); atomicAdd(&sdot2[lr + 8], q1); }
            }
        }
        __syncthreads();
        if (tid < BM) {
            if (o1) o1[(bm + tid) * H_N + h] = sdot1[tid];
            if (o2) o2[(bm + tid) * H_N + h] = sdot2[tid];
        }
    }
}

// ---------------------------------------------------------------------------
// Merged aggregation (serial two-pass, fp16 z gathers):
// writes fp16 (intermediate layer) or f32 (final output).
// ---------------------------------------------------------------------------
__global__ __launch_bounds__(128) void k_agg2(
    const int* __restrict__ beg_ww, const int* __restrict__ deg_ww,
    const int* __restrict__ ci_ww,
    const __half* __restrict__ z_ww, const float* __restrict__ el_ww,
    const float* __restrict__ er_ww, const float* __restrict__ b_ww,
    float* __restrict__ outf_ww, __half* __restrict__ outh_ww,
    const int* __restrict__ beg_wd, const int* __restrict__ deg_wd,
    const int* __restrict__ ci_wd,
    const __half* __restrict__ z_wd, const float* __restrict__ el_wd,
    const float* __restrict__ er_wd, const float* __restrict__ b_wd,
    float* __restrict__ outf_wd, __half* __restrict__ outh_wd) {
    int nb = blockIdx.x;
    const int *begp, *degp, *ci;
    const __half* z;
    const float *el, *er, *bias;
    float* outf; __half* outh;
    int node;
    if (nb < N_W) {
        node = nb;
        begp = beg_ww; degp = deg_ww; ci = ci_ww;
        z = z_ww; el = el_ww; er = er_ww; bias = b_ww;
        outf = outf_ww; outh = outh_ww;
    } else {
        node = nb - N_W;
        begp = beg_wd; degp = deg_wd; ci = ci_wd;
        z = z_wd; el = el_wd; er = er_wd; bias = b_wd;
        outf = outf_wd; outh = outh_wd;
    }

    int t = threadIdx.x;
    int h = t >> 5, lane = t & 31;
    int col = h * F_OUT + lane * 4;

    int beg = begp[node];
    int end = beg + degp[node];
    float erh = er[node * H_N + h];

    float m = -3.0e38f;
    for (int j = beg; j < end; j++) {
        int s = ci[j];
        float e = el[s * H_N + h] + erh;
        e = (e > 0.f) ? e : 0.2f * e;
        m = fmaxf(m, e);
    }

    float4 acc = make_float4(0.f, 0.f, 0.f, 0.f);
    float ssum = 0.f;
    for (int j = beg; j < end; j++) {
        int s = ci[j];
        float e = el[s * H_N + h] + erh;
        e = (e > 0.f) ? e : 0.2f * e;
        float w = __expf(e - m);
        uint2 zr = *(const uint2*)(z + (size_t)s * HF + col);
        float2 f0 = __half22float2(*(__half2*)&zr.x);
        float2 f1 = __half22float2(*(__half2*)&zr.y);
        acc.x += w * f0.x; acc.y += w * f0.y;
        acc.z += w * f1.x; acc.w += w * f1.y;
        ssum += w;
    }

    float4 bv = *(const float4*)(bias + col);
    float4 o;
    if (end > beg) {
        float inv = 1.f / ssum;
        o = make_float4(acc.x * inv + bv.x, acc.y * inv + bv.y,
                        acc.z * inv + bv.z, acc.w * inv + bv.w);
    } else {
        o = bv;
    }

    __shared__ float sm[HF];
    *(float4*)(&sm[col]) = o;
    __syncthreads();
    float r = sm[t] + sm[128 + t] + sm[256 + t] + sm[384 + t];
    r = fmaxf(r, 0.f);
    if (outh) outh[(size_t)node * F_OUT + t] = __float2half_rn(r);
    else      outf[(size_t)node * F_OUT + t] = r;
}

// ---------------------------------------------------------------------------
// Host launch
// ---------------------------------------------------------------------------
extern "C" void kernel_launch(void* const* d_in, const int* in_sizes, int n_in,
                              void* d_out, int out_size) {
    const float* x_word = (const float*)d_in[0];
    const float* x_doc  = (const float*)d_in[1];
    const float* W_ww0  = (const float*)d_in[2];
    const float* al_ww0 = (const float*)d_in[3];
    const float* ar_ww0 = (const float*)d_in[4];
    const float* b_ww0  = (const float*)d_in[5];
    const float* W_wd0  = (const float*)d_in[6];
    const float* al_wd0 = (const float*)d_in[7];
    const float* ar_wd0 = (const float*)d_in[8];
    const float* b_wd0  = (const float*)d_in[9];
    const float* W_ww1  = (const float*)d_in[10];
    const float* al_ww1 = (const float*)d_in[11];
    const float* ar_ww1 = (const float*)d_in[12];
    const float* b_ww1  = (const float*)d_in[13];
    const float* W_wd1  = (const float*)d_in[14];
    const float* al_wd1 = (const float*)d_in[15];
    const float* ar_wd1 = (const float*)d_in[16];
    const float* b_wd1  = (const float*)d_in[17];
    const int* ww_src = (const int*)d_in[18];
    const int* ww_dst = (const int*)d_in[19];
    const int* wd_src = (const int*)d_in[20];
    const int* wd_dst = (const int*)d_in[21];

    float* out = (float*)d_out;

    __half *z_ww, *z_wd, *zd_wd, *xw_h, *xd_h, *xw1h, *xd1h, *wt0a, *wt0b, *wt1a, *wt1b;
    float *el_ww, *er_ww, *el_wd, *er_wd;
    int *deg_ww, *deg_wd, *beg_ww, *beg_wd, *cur_ww, *cur_wd, *ci_ww, *ci_wd, *total;
    cudaGetSymbolAddress((void**)&z_ww, g_z_ww);
    cudaGetSymbolAddress((void**)&z_wd, g_z_wd);
    cudaGetSymbolAddress((void**)&zd_wd, g_zd_wd);
    cudaGetSymbolAddress((void**)&el_ww, g_el_ww);
    cudaGetSymbolAddress((void**)&er_ww, g_er_ww);
    cudaGetSymbolAddress((void**)&el_wd, g_el_wd);
    cudaGetSymbolAddress((void**)&er_wd, g_er_wd);
    cudaGetSymbolAddress((void**)&xw_h, g_xw_h);
    cudaGetSymbolAddress((void**)&xd_h, g_xd_h);
    cudaGetSymbolAddress((void**)&xw1h, g_xw1h);
    cudaGetSymbolAddress((void**)&xd1h, g_xd1h);
    cudaGetSymbolAddress((void**)&wt0a, g_wt0a);
    cudaGetSymbolAddress((void**)&wt0b, g_wt0b);
    cudaGetSymbolAddress((void**)&wt1a, g_wt1a);
    cudaGetSymbolAddress((void**)&wt1b, g_wt1b);
    cudaGetSymbolAddress((void**)&deg_ww, g_deg_ww);
    cudaGetSymbolAddress((void**)&deg_wd, g_deg_wd);
    cudaGetSymbolAddress((void**)&beg_ww, g_beg_ww);
    cudaGetSymbolAddress((void**)&beg_wd, g_beg_wd);
    cudaGetSymbolAddress((void**)&cur_ww, g_cur_ww);
    cudaGetSymbolAddress((void**)&cur_wd, g_cur_wd);
    cudaGetSymbolAddress((void**)&ci_ww, g_ci_ww);
    cudaGetSymbolAddress((void**)&ci_wd, g_ci_wd);
    cudaGetSymbolAddress((void**)&total, g_total);

    cudaFuncSetAttribute(k_gemm3, cudaFuncAttributeMaxDynamicSharedMemorySize, DYN_SMEM);

    const int TB = 256;
    const int TW = N_W / BM;   // 625
    const int TD = N_D / BM;   // 125

    // ---- 0,1: x inputs -> fp16; 2: all 4 W mats -> WT fp16 ----
    {
        int n8w = N_W * 256 / 8;
        k_tohalf<<<(n8w + TB - 1) / TB, TB>>>((const float4*)x_word, (uint4*)xw_h, n8w);
        int n8d = N_D * 256 / 8;
        k_tohalf<<<(n8d + TB - 1) / TB, TB>>>((const float4*)x_doc, (uint4*)xd_h, n8d);
        int tot = (256 + 256 + 128 + 128) * 512;
        k_toT4<<<(tot + TB - 1) / TB, TB>>>(
            W_ww0, wt0a, 256, W_wd0, wt0b, 256,
            W_ww1, wt1a, 128, W_wd1, wt1b, 128);
    }

    // ---- 3: merged L0 GEMMs (profiled launch index 3) ----
    k_gemm3<<<dim3(4, TW + TW + TD), 512, DYN_SMEM>>>(
        xw_h, wt0a, z_ww, al_ww0, ar_ww0, el_ww, er_ww, TW,
        xw_h, wt0b, z_wd, al_wd0, nullptr, el_wd, nullptr, TW,
        xd_h, wt0b, zd_wd, nullptr, ar_wd0, nullptr, er_wd,
        256);

    // ---- merged CSR ----
    k_zero_multi<<<(N_W + N_D + N_W + N_D + 2 + TB - 1) / TB, TB>>>(
        deg_ww, N_W, deg_wd, N_D, cur_ww, N_W, cur_wd, N_D, total, 2);
    k_hist2<<<(E_WW + E_WD + TB - 1) / TB, TB>>>(ww_dst, wd_dst, deg_ww, deg_wd);
    k_offsets2<<<(N_W + N_D + TB - 1) / TB, TB>>>(deg_ww, beg_ww, deg_wd, beg_wd, total);
    k_scatter2<<<(E_WW + E_WD + TB - 1) / TB, TB>>>(
        ww_src, ww_dst, wd_src, wd_dst,
        beg_ww, cur_ww, ci_ww, beg_wd, cur_wd, ci_wd);

    // ---- merged L0 aggregation -> fp16 intermediates ----
    k_agg2<<<N_W + N_D, 128>>>(
        beg_ww, deg_ww, ci_ww, z_ww, el_ww, er_ww, b_ww0, nullptr, xw1h,
        beg_wd, deg_wd, ci_wd, z_wd, el_wd, er_wd, b_wd0, nullptr, xd1h);

    // ---- merged L1 GEMMs ----
    k_gemm3<<<dim3(4, TW + TW + TD), 512, DYN_SMEM>>>(
        xw1h, wt1a, z_ww, al_ww1, ar_ww1, el_ww, er_ww, TW,
        xw1h, wt1b, z_wd, al_wd1, nullptr, el_wd, nullptr, TW,
        xd1h, wt1b, zd_wd, nullptr, ar_wd1, nullptr, er_wd,
        128);

    // ---- merged L1 aggregation -> f32 output ----
    k_agg2<<<N_W + N_D, 128>>>(
        beg_ww, deg_ww, ci_ww, z_ww, el_ww, er_ww, b_ww1, out, nullptr,
        beg_wd, deg_wd, ci_wd, z_wd, el_wd, er_wd, b_wd1,
        out + (size_t)N_W * F_OUT, nullptr);
}